// round 15
// baseline (speedup 1.0000x reference)
#include <cuda_runtime.h>
#include <cuda_fp16.h>
#include <math.h>

#define BATCHES 8
#define NMAX    128
#define PE      64
#define NE      5
#define DS      64
#define NF      8
#define TOTAL   (BATCHES*NMAX)
#define PROJC   (4*NE*PE)

#define OFF_EHAT 0
#define OFF_XHAT (BATCHES*NMAX*NMAX*NE)
#define OFF_EDGE (OFF_XHAT + TOTAL*NF)
#define OFF_MASK (OFF_EDGE + BATCHES*NMAX*NMAX)

typedef unsigned long long ull;
typedef unsigned int uint;

__device__ __half g_projh[TOTAL*PROJC];
__device__ int    g_cnt[BATCHES];
__device__ float  g_coef[BATCHES];
__device__ float  g_u[DS];
__device__ float  g_v[DS];
__device__ float  g_dct[14*14];
__device__ float  g_cheb[14];

#define FMA2(d,a,b,c) asm("fma.rn.f32x2 %0, %1, %2, %3;" : "=l"(d) : "l"(a), "l"(b), "l"(c))
#define MUL2(d,a,b)   asm("mul.rn.f32x2 %0, %1, %2;" : "=l"(d) : "l"(a), "l"(b))
#define ADD2(d,a,b)   asm("add.rn.f32x2 %0, %1, %2;" : "=l"(d) : "l"(a), "l"(b))
#define PACK2(d,lo,hi) asm("mov.b64 %0, {%1, %2};" : "=l"(d) : "r"(__float_as_uint(lo)), "r"(__float_as_uint(hi)))

#define HMMA16816(c0,c1,c2,c3,a0,a1,a2,a3,b0,b1) \
    asm volatile("mma.sync.aligned.m16n8k16.row.col.f32.f16.f16.f32 " \
        "{%0,%1,%2,%3}, {%4,%5,%6,%7}, {%8,%9}, {%0,%1,%2,%3};" \
        : "+f"(c0), "+f"(c1), "+f"(c2), "+f"(c3) \
        : "r"(a0), "r"(a1), "r"(a2), "r"(a3), "r"(b0), "r"(b1))

__device__ __forceinline__ ull dup2(float v) { ull d; PACK2(d, v, v); return d; }
__device__ __forceinline__ float lo2(ull v) { return __uint_as_float((uint)v); }
__device__ __forceinline__ float hi2(ull v) { return __uint_as_float((uint)(v >> 32)); }

__device__ __forceinline__ int lbound(const int* __restrict__ a, int n, int v) {
    int lo = 0, hi = n;
    while (lo < hi) {
        int m = (lo + hi) >> 1;
        if (a[m] < v) lo = m + 1; else hi = m;
    }
    return lo;
}

// erf(x/sqrt(2)) = x * (C0 + C1 x^2 + ... + C5 x^10), |x|<=1.5
#define C0  0.7978845608028654f
#define C1 (-0.13298076013381092f)
#define C2  0.019947114020071635f
#define C3 (-0.0023746564309608790f)
#define C4  2.3087512708529163e-4f
#define C5 (-1.8888357703977833e-5f)
#define PI_F 3.14159265358979323846f

// ---------------------------------------------------------------------------
// K1: proj GEMM (fp32 compute, fp16 store) + x_hat (bx==20) + prep (bx==21).
// ---------------------------------------------------------------------------
struct PSmemGemm { ull Ad[64][64]; ull Wp[64][32]; };
struct PSmemPrep { float ru[4][64]; float rv[4][64]; int start[12]; };

__global__ void __launch_bounds__(256) k_projx(
        const float* __restrict__ x, const float* __restrict__ w,
        const float* __restrict__ bias,
        const float* __restrict__ w_node, const float* __restrict__ b_node,
        const int* __restrict__ batch, const float* __restrict__ q,
        const float* __restrict__ w_phi, const float* __restrict__ b_phi,
        const float* __restrict__ w_ctx,
        float* __restrict__ out_xhat, float* __restrict__ out_mask) {
    __shared__ union { PSmemGemm g; PSmemPrep p; } su;
    int tid = threadIdx.x;
    if (blockIdx.x == 20) {             // x_hat
        int base = blockIdx.y * 512;
        #pragma unroll
        for (int l = 0; l < 2; l++) {
            int id = base + tid + l*256;
            int node = id / NF, f = id % NF;
            float acc = 0.f;
            #pragma unroll 8
            for (int k = 0; k < PE; k++)
                acc = fmaf(__ldg(&x[node*PE + k]), __ldg(&w_node[k*NF + f]), acc);
            out_xhat[id] = acc + b_node[f];
        }
        return;
    }
    if (blockIdx.x == 21) {             // prep
        if (blockIdx.y) return;
        if (tid < 9) su.p.start[tid] = lbound(batch, TOTAL, tid);
        if (tid < 196) {
            int k = tid / 14, j = tid % 14;
            float th = (float)(2*j + 1) * (PI_F / 28.0f);
            float sk = (k == 0) ? (1.0f/14.0f) : (2.0f/14.0f);
            g_dct[tid] = sk * cosf((float)k * th);
            if (k == 0) g_cheb[j] = cosf(th);
        }
        int d = tid & 63, qd = tid >> 6;
        float u = 0.f, v = 0.f;
        #pragma unroll
        for (int k = qd*16; k < qd*16 + 16; k++) {
            float wc = w_ctx[k*DS + d];
            u = fmaf(w_phi[k], wc, u);
            v = fmaf(b_phi[k], wc, v);
        }
        su.p.ru[qd][d] = u;
        su.p.rv[qd][d] = v;
        __syncthreads();
        if (qd == 0) {
            g_u[d] = su.p.ru[0][d] + su.p.ru[1][d] + su.p.ru[2][d] + su.p.ru[3][d];
            g_v[d] = su.p.rv[0][d] + su.p.rv[1][d] + su.p.rv[2][d] + su.p.rv[3][d];
        }
        if (tid < BATCHES) {
            g_cnt[tid] = su.p.start[tid+1] - su.p.start[tid];
            float qq = q[tid];
            float c = cosf(6.283185307179586f*qq);
            float s = sinf(6.283185307179586f*qq);
            g_coef[tid] = (2.0f - c) / s;
        }
        #pragma unroll
        for (int l = 0; l < 4; l++) {
            int idx = tid + l*256;
            int bb = idx >> 7, pos = idx & 127;
            int cnt = su.p.start[bb+1] - su.p.start[bb];
            out_mask[idx] = (pos < cnt) ? 1.0f : 0.0f;
        }
        return;
    }
    // ---- main GEMM blocks ----
    int row0 = blockIdx.y * 64;
    int col0 = blockIdx.x * 64;
    int bb = row0 >> 7;
    int sb_start = lbound(batch, TOTAL, bb);
    int sb_cnt   = lbound(batch, TOTAL, bb+1) - sb_start;
    int tx = tid & 15, ty = tid >> 4;
    #pragma unroll
    for (int l = 0; l < 4; l++) {
        int e = tid + l*256;
        int r = e >> 4, kq = (e & 15) * 4;
        int pos = (row0 + r) & 127;
        float4 v = make_float4(0.f,0.f,0.f,0.f);
        if (pos < sb_cnt) v = *(const float4*)&x[(sb_start + pos)*PE + kq];
        su.g.Ad[r][kq+0] = dup2(v.x);
        su.g.Ad[r][kq+1] = dup2(v.y);
        su.g.Ad[r][kq+2] = dup2(v.z);
        su.g.Ad[r][kq+3] = dup2(v.w);
    }
    #pragma unroll
    for (int l = 0; l < 4; l++) {
        int e = tid + l*256;
        int k = e >> 4, cq = (e & 15) * 4;
        float4 v = *(const float4*)&w[k*PROJC + col0 + cq];
        ull p0, p1;
        PACK2(p0, v.x, v.y);
        PACK2(p1, v.z, v.w);
        su.g.Wp[k][cq/2]   = p0;
        su.g.Wp[k][cq/2+1] = p1;
    }
    __syncthreads();
    ull acc[4][2];
    #pragma unroll
    for (int i = 0; i < 4; i++) { acc[i][0] = 0ull; acc[i][1] = 0ull; }
    #pragma unroll 4
    for (int kk = 0; kk < 64; kk += 2) {
        ulonglong2 ai[4];
        #pragma unroll
        for (int i = 0; i < 4; i++)
            ai[i] = *(const ulonglong2*)&su.g.Ad[ty + 16*i][kk];
        ull b00 = su.g.Wp[kk][tx],   b10 = su.g.Wp[kk][tx+16];
        ull b01 = su.g.Wp[kk+1][tx], b11 = su.g.Wp[kk+1][tx+16];
        #pragma unroll
        for (int i = 0; i < 4; i++) {
            FMA2(acc[i][0], ai[i].x, b00, acc[i][0]);
            FMA2(acc[i][0], ai[i].y, b01, acc[i][0]);
            FMA2(acc[i][1], ai[i].x, b10, acc[i][1]);
            FMA2(acc[i][1], ai[i].y, b11, acc[i][1]);
        }
    }
    #pragma unroll
    for (int i = 0; i < 4; i++) {
        int r = row0 + ty + 16*i;
        int valid = ((r & 127) < sb_cnt);
        #pragma unroll
        for (int j = 0; j < 2; j++) {
            int cp = tx + 16*j;
            int c = col0 + 2*cp;
            float v0 = 0.f, v1 = 0.f;
            if (valid) {
                v0 = lo2(acc[i][j]) + bias[c];
                v1 = hi2(acc[i][j]) + bias[c+1];
            }
            *(__half2*)&g_projh[r*PROJC + c] = __floats2half2_rn(v0, v1);
        }
    }
}

// ---------------------------------------------------------------------------
// K2 (fused, HMMA, 256 threads): fp16 proj in GMEM -> pure-copy fills.
// A = [k1|coef*k2] (16x128), B = [q1|q2] (128x128, k-contig, pad 136).
// Warp w owns 16 n-cols (2 n-tiles, 16 HMMA). Epilogue as proven.
// ---------------------------------------------------------------------------
#define HPAD 136
struct SmemGemm { unsigned short Ks[16][HPAD]; unsigned short Qs[128][HPAD]; };
struct SmemEpi  {
    float a[16][64];
    float nod[16][16];
    ull   ck[16][14];
    ull   ws2[64];
    ull   w2d[64];
    float alpha[16], rho[16], zmax[16], rinv[16];
    float psum[16][8], pmax[16][8];
};

__global__ void __launch_bounds__(256) k_zmain(
        const float* __restrict__ w_self, const float* __restrict__ b_self,
        const float* __restrict__ w_out, const float* __restrict__ b_out,
        float* __restrict__ out_e, float* __restrict__ out_edge) {
    __shared__ union { SmemGemm g; SmemEpi e; } su;
    __shared__ float s_maskf[NMAX];
    const float scale = 0.05590169943749474f;   // 1/sqrt(320)
    int tid = threadIdx.x;
    int lane = tid & 31, w = tid >> 5;          // 8 warps
    int gid = lane >> 2, tig = lane & 3;        // mma fragment coords
    int tile = blockIdx.x, e = blockIdx.y, b = blockIdx.z;
    int row0 = tile * 16;
    int base_row = b * NMAX;
    int cnt = g_cnt[b];
    float coef = g_coef[b];
    if (tid < NMAX) s_maskf[tid] = (tid < cnt) ? 1.0f : 0.0f;

    int koff1 = e*PE, koff2 = 2*NE*PE + e*PE;
    int qoff1 = NE*PE + e*PE, qoff2 = 3*NE*PE + e*PE;

    // ---- K fill: 16 rows x 16 chunks of 8 halves, one LDG.128/thread.
    //      coef folded into k2 half (fp32-precision multiply).
    {
        int r = tid >> 4, c = tid & 15;
        const __half* src = (c < 8)
            ? &g_projh[(base_row + row0 + r)*PROJC + koff1 + c*8]
            : &g_projh[(base_row + row0 + r)*PROJC + koff2 + (c-8)*8];
        uint4 v = *(const uint4*)src;
        if (c >= 8) {
            __half2* hp = (__half2*)&v;
            #pragma unroll
            for (int t = 0; t < 4; t++) {
                float2 f = __half22float2(hp[t]);
                hp[t] = __floats2half2_rn(f.x*coef, f.y*coef);
            }
        }
        *(uint4*)&su.g.Ks[r][c*8] = v;
    }
    // ---- Q fill: pure 16B copy, 8 per thread ----
    #pragma unroll
    for (int l = 0; l < 8; l++) {
        int e4 = tid + l*256;
        int m = e4 >> 4, c = e4 & 15;
        const __half* src = (c < 8)
            ? &g_projh[(base_row + m)*PROJC + qoff1 + c*8]
            : &g_projh[(base_row + m)*PROJC + qoff2 + (c-8)*8];
        *(uint4*)&su.g.Qs[m][c*8] = *(const uint4*)src;
    }
    __syncthreads();

    // ---- HMMA mainloop: M=16, N=16 (per warp), K=128 ----
    float acc[2][4];
    #pragma unroll
    for (int nt = 0; nt < 2; nt++)
        #pragma unroll
        for (int j = 0; j < 4; j++) acc[nt][j] = 0.f;
    #pragma unroll
    for (int kc = 0; kc < 8; kc++) {
        int k0 = kc*16 + 2*tig;
        uint a0 = *(const uint*)&su.g.Ks[gid  ][k0];
        uint a1 = *(const uint*)&su.g.Ks[gid+8][k0];
        uint a2 = *(const uint*)&su.g.Ks[gid  ][k0+8];
        uint a3 = *(const uint*)&su.g.Ks[gid+8][k0+8];
        #pragma unroll
        for (int nt = 0; nt < 2; nt++) {
            int n = 16*w + nt*8 + gid;
            uint b0 = *(const uint*)&su.g.Qs[n][k0];
            uint b1 = *(const uint*)&su.g.Qs[n][k0+8];
            HMMA16816(acc[nt][0], acc[nt][1], acc[nt][2], acc[nt][3],
                      a0, a1, a2, a3, b0, b1);
        }
    }
    #pragma unroll
    for (int nt = 0; nt < 2; nt++)
        #pragma unroll
        for (int j = 0; j < 4; j++) acc[nt][j] *= scale;

    __syncthreads();    // GEMM tiles dead; epilogue aliases su

    // ---- Phase B: row sums / zmax (fragment-aware) ----
    {
        int n0g = row0 + gid, n1g = row0 + gid + 8;
        float s0 = 0.f, s1 = 0.f, zm0 = 0.f, zm1 = 0.f;
        #pragma unroll
        for (int nt = 0; nt < 2; nt++) {
            int m = 16*w + nt*8 + 2*tig;
            float w0a = s_maskf[m]   * (float)(m   != n0g);
            float w0b = s_maskf[m+1] * (float)(m+1 != n0g);
            float w1a = s_maskf[m]   * (float)(m   != n1g);
            float w1b = s_maskf[m+1] * (float)(m+1 != n1g);
            s0 = fmaf(acc[nt][0], w0a, fmaf(acc[nt][1], w0b, s0));
            s1 = fmaf(acc[nt][2], w1a, fmaf(acc[nt][3], w1b, s1));
            zm0 = fmaxf(zm0, fmaxf(fabsf(acc[nt][0]), fabsf(acc[nt][1])));
            zm1 = fmaxf(zm1, fmaxf(fabsf(acc[nt][2]), fabsf(acc[nt][3])));
        }
        #pragma unroll
        for (int off = 1; off <= 2; off <<= 1) {
            s0 += __shfl_xor_sync(0xffffffffu, s0, off);
            s1 += __shfl_xor_sync(0xffffffffu, s1, off);
            zm0 = fmaxf(zm0, __shfl_xor_sync(0xffffffffu, zm0, off));
            zm1 = fmaxf(zm1, __shfl_xor_sync(0xffffffffu, zm1, off));
        }
        if (tig == 0) {
            su.e.psum[gid  ][w] = s0;
            su.e.psum[gid+8][w] = s1;
            su.e.pmax[gid  ][w] = zm0;
            su.e.pmax[gid+8][w] = zm1;
        }
        if (tid >= 128 && tid < 192) {
            int d = tid - 128;
            su.e.ws2[d] = dup2(w_self[d]);
            su.e.w2d[d] = dup2(0.5f * w_out[d]);
        }
    }
    __syncthreads();
    if (tid < 16) {
        int r = tid;
        float s = 0.f, zm = 0.f;
        #pragma unroll
        for (int j = 0; j < 8; j++) {
            s += su.e.psum[r][j];
            zm = fmaxf(zm, su.e.pmax[r][j]);
        }
        int mn = ((row0 + r) < cnt);
        float cm1 = (float)(cnt - 1);
        float denom = fmaxf(cm1, 1.0f);
        su.e.alpha[r] = mn ? (s / denom) : 0.0f;
        su.e.rho[r]   = mn ? (cm1 / denom) : 0.0f;
        float zmx = fmaxf(zm, 1e-20f);
        su.e.zmax[r]  = zmx;
        su.e.rinv[r]  = 1.0f / zmx;
    }
    __syncthreads();

    // ---- Phase C1: per-row gelu offsets ----
    #pragma unroll
    for (int l = 0; l < 4; l++) {
        int idx = tid + l*256;
        int row = idx >> 6, d = idx & 63;
        su.e.a[row][d] = fmaf(su.e.alpha[row], g_u[d],
                              fmaf(su.e.rho[row], g_v[d], b_self[d]));
    }
    __syncthreads();

    // ---- Phase C2: nodal sums (thread = row x node-pair) ----
    if (tid < 112) {
        int row = tid / 7;
        int np  = tid - row*7;
        float zmaxr = su.e.zmax[row];
        float znl = zmaxr * g_cheb[2*np];
        float znh = zmaxr * g_cheb[2*np+1];
        ull zn; PACK2(zn, znl, znh);
        const ull k0 = dup2(C0), k1 = dup2(C1), k2 = dup2(C2);
        const ull k3 = dup2(C3), k4 = dup2(C4), k5 = dup2(C5);
        ull acc2 = 0ull;
        float tmax = 0.f;
        #pragma unroll 8
        for (int d = 0; d < 64; d++) {
            ull ad = dup2(su.e.a[row][d]);
            ull xx, tt, p;
            FMA2(xx, su.e.ws2[d], zn, ad);
            MUL2(tt, xx, xx);
            p = k5;
            FMA2(p, p, tt, k4);
            FMA2(p, p, tt, k3);
            FMA2(p, p, tt, k2);
            FMA2(p, p, tt, k1);
            FMA2(p, p, tt, k0);
            ull h;
            FMA2(h, tt, p, xx);
            FMA2(acc2, su.e.w2d[d], h, acc2);
            tmax = fmaxf(tmax, fmaxf(lo2(tt), hi2(tt)));
        }
        if (tmax > 2.25f) {
            float al = 0.f, ah = 0.f;
            for (int d = 0; d < 64; d++) {
                float a = su.e.a[row][d];
                float ws = lo2(su.e.ws2[d]);
                float w2 = lo2(su.e.w2d[d]);
                float x0 = fmaf(ws, znl, a), x1 = fmaf(ws, znh, a);
                al = fmaf(w2, x0*(1.f + erff(x0*0.7071067811865476f)), al);
                ah = fmaf(w2, x1*(1.f + erff(x1*0.7071067811865476f)), ah);
            }
            PACK2(acc2, al, ah);
        }
        su.e.nod[row][2*np]   = lo2(acc2);
        su.e.nod[row][2*np+1] = hi2(acc2);
    }
    __syncthreads();

    // ---- Phase C3: DCT -> Chebyshev coefficients (b_out folded into c0) ----
    float bo = b_out[0];
    if (tid < 224) {
        int row = tid / 14, k = tid - row*14;
        float c = 0.f;
        #pragma unroll
        for (int j = 0; j < 14; j++)
            c = fmaf(__ldg(&g_dct[k*14 + j]), su.e.nod[row][j], c);
        if (k == 0) c += bo;
        su.e.ck[row][k] = dup2(c);
    }
    __syncthreads();

    // ---- Phase D: packed Clenshaw on register fragments + stores ----
    ull negone = dup2(-1.0f);
    #pragma unroll
    for (int rr = 0; rr < 2; rr++) {
        int rloc = gid + 8*rr;
        int n = row0 + rloc;
        ull rinv2 = dup2(su.e.rinv[rloc]);
        ull sv[2], svx[2], b1[2], b2[2];
        #pragma unroll
        for (int nt = 0; nt < 2; nt++) {
            ull z2; PACK2(z2, acc[nt][2*rr], acc[nt][2*rr+1]);
            MUL2(sv[nt], z2, rinv2);
            ADD2(svx[nt], sv[nt], sv[nt]);
            b1[nt] = 0ull; b2[nt] = 0ull;
        }
        #pragma unroll
        for (int k = 13; k >= 1; k--) {
            ull ckk = su.e.ck[rloc][k];
            #pragma unroll
            for (int nt = 0; nt < 2; nt++) {
                ull nb;
                FMA2(nb, svx[nt], b1[nt], ckk);
                FMA2(nb, b2[nt], negone, nb);
                b2[nt] = b1[nt]; b1[nt] = nb;
            }
        }
        ull ck0 = su.e.ck[rloc][0];
        #pragma unroll
        for (int nt = 0; nt < 2; nt++) {
            ull f;
            FMA2(f, sv[nt], b1[nt], ck0);
            FMA2(f, b2[nt], negone, f);
            int m = 16*w + nt*8 + 2*tig;
            out_e[((long)(b*NMAX + m  )*NMAX + n)*NE + e] = lo2(f);
            out_e[((long)(b*NMAX + m+1)*NMAX + n)*NE + e] = hi2(f);
        }
        if (e == 0) {
            float mkn = s_maskf[n];
            #pragma unroll
            for (int nt = 0; nt < 2; nt++) {
                int m = 16*w + nt*8 + 2*tig;
                float2 v = make_float2(mkn*s_maskf[m]  *(float)(n != m),
                                       mkn*s_maskf[m+1]*(float)(n != m+1));
                *(float2*)&out_edge[(b*NMAX + n)*NMAX + m] = v;
            }
        }
    }
}

extern "C" void kernel_launch(void* const* d_in, const int* in_sizes, int n_in,
                              void* d_out, int out_size) {
    const float* x      = (const float*)d_in[0];
    const int*   batch  = (const int*)  d_in[1];
    const float* q      = (const float*)d_in[2];
    const float* w_attn = (const float*)d_in[3];
    const float* b_attn = (const float*)d_in[4];
    const float* w_node = (const float*)d_in[5];
    const float* b_node = (const float*)d_in[6];
    const float* w_phi  = (const float*)d_in[7];
    const float* b_phi  = (const float*)d_in[8];
    const float* w_ctx  = (const float*)d_in[9];
    const float* w_self = (const float*)d_in[10];
    const float* b_self = (const float*)d_in[11];
    const float* w_out  = (const float*)d_in[12];
    const float* b_out  = (const float*)d_in[13];
    float* out = (float*)d_out;

    k_projx<<<dim3(22, 16), 256>>>(x, w_attn, b_attn, w_node, b_node,
                                   batch, q, w_phi, b_phi, w_ctx,
                                   out + OFF_XHAT, out + OFF_MASK);
    k_zmain<<<dim3(8, NE, BATCHES), 256>>>(w_self, b_self, w_out, b_out,
                                           out + OFF_EHAT, out + OFF_EDGE);
}

// round 16
// speedup vs baseline: 1.1778x; 1.1778x over previous
#include <cuda_runtime.h>
#include <cuda_fp16.h>
#include <math.h>

#define BATCHES 8
#define NMAX    128
#define PE      64
#define NE      5
#define DS      64
#define NF      8
#define TOTAL   (BATCHES*NMAX)
#define PROJC   (4*NE*PE)

#define OFF_EHAT 0
#define OFF_XHAT (BATCHES*NMAX*NMAX*NE)
#define OFF_EDGE (OFF_XHAT + TOTAL*NF)
#define OFF_MASK (OFF_EDGE + BATCHES*NMAX*NMAX)

typedef unsigned long long ull;
typedef unsigned int uint;

__device__ __half g_projh[TOTAL*PROJC];
__device__ int    g_cnt[BATCHES];
__device__ float  g_coef[BATCHES];
__device__ float  g_u[DS];
__device__ float  g_v[DS];
__device__ float  g_dct[14*14];
__device__ float  g_cheb[14];

#define FMA2(d,a,b,c) asm("fma.rn.f32x2 %0, %1, %2, %3;" : "=l"(d) : "l"(a), "l"(b), "l"(c))
#define MUL2(d,a,b)   asm("mul.rn.f32x2 %0, %1, %2;" : "=l"(d) : "l"(a), "l"(b))
#define ADD2(d,a,b)   asm("add.rn.f32x2 %0, %1, %2;" : "=l"(d) : "l"(a), "l"(b))
#define PACK2(d,lo,hi) asm("mov.b64 %0, {%1, %2};" : "=l"(d) : "r"(__float_as_uint(lo)), "r"(__float_as_uint(hi)))

#define HMMA16816(c0,c1,c2,c3,a0,a1,a2,a3,b0,b1) \
    asm volatile("mma.sync.aligned.m16n8k16.row.col.f32.f16.f16.f32 " \
        "{%0,%1,%2,%3}, {%4,%5,%6,%7}, {%8,%9}, {%0,%1,%2,%3};" \
        : "+f"(c0), "+f"(c1), "+f"(c2), "+f"(c3) \
        : "r"(a0), "r"(a1), "r"(a2), "r"(a3), "r"(b0), "r"(b1))

__device__ __forceinline__ ull dup2(float v) { ull d; PACK2(d, v, v); return d; }
__device__ __forceinline__ float lo2(ull v) { return __uint_as_float((uint)v); }
__device__ __forceinline__ float hi2(ull v) { return __uint_as_float((uint)(v >> 32)); }

__device__ __forceinline__ int lbound(const int* __restrict__ a, int n, int v) {
    int lo = 0, hi = n;
    while (lo < hi) {
        int m = (lo + hi) >> 1;
        if (a[m] < v) lo = m + 1; else hi = m;
    }
    return lo;
}

// erf(x/sqrt(2)) = x * (C0 + C1 x^2 + ... + C5 x^10), |x|<=1.5
#define C0  0.7978845608028654f
#define C1 (-0.13298076013381092f)
#define C2  0.019947114020071635f
#define C3 (-0.0023746564309608790f)
#define C4  2.3087512708529163e-4f
#define C5 (-1.8888357703977833e-5f)
#define PI_F 3.14159265358979323846f

// ---------------------------------------------------------------------------
// K1: proj GEMM on tensor cores (fp16 in, fp32 accum, fp16 store)
//     + x_hat (bx==20) + prep (bx==21).
// ---------------------------------------------------------------------------
struct PSmemGemm { __half Xs[64][72]; __half Ws[64][70]; };
struct PSmemPrep { float ru[4][64]; float rv[4][64]; int start[12]; };

__global__ void __launch_bounds__(256) k_projx(
        const float* __restrict__ x, const float* __restrict__ w,
        const float* __restrict__ bias,
        const float* __restrict__ w_node, const float* __restrict__ b_node,
        const int* __restrict__ batch, const float* __restrict__ q,
        const float* __restrict__ w_phi, const float* __restrict__ b_phi,
        const float* __restrict__ w_ctx,
        float* __restrict__ out_xhat, float* __restrict__ out_mask) {
    __shared__ union { PSmemGemm g; PSmemPrep p; } su;
    int tid = threadIdx.x;
    if (blockIdx.x == 20) {             // x_hat
        int base = blockIdx.y * 512;
        #pragma unroll
        for (int l = 0; l < 2; l++) {
            int id = base + tid + l*256;
            int node = id / NF, f = id % NF;
            float acc = 0.f;
            #pragma unroll 8
            for (int k = 0; k < PE; k++)
                acc = fmaf(__ldg(&x[node*PE + k]), __ldg(&w_node[k*NF + f]), acc);
            out_xhat[id] = acc + b_node[f];
        }
        return;
    }
    if (blockIdx.x == 21) {             // prep
        if (blockIdx.y) return;
        if (tid < 9) su.p.start[tid] = lbound(batch, TOTAL, tid);
        if (tid < 196) {
            int k = tid / 14, j = tid % 14;
            float th = (float)(2*j + 1) * (PI_F / 28.0f);
            float sk = (k == 0) ? (1.0f/14.0f) : (2.0f/14.0f);
            g_dct[tid] = sk * cosf((float)k * th);
            if (k == 0) g_cheb[j] = cosf(th);
        }
        int d = tid & 63, qd = tid >> 6;
        float u = 0.f, v = 0.f;
        #pragma unroll
        for (int k = qd*16; k < qd*16 + 16; k++) {
            float wc = w_ctx[k*DS + d];
            u = fmaf(w_phi[k], wc, u);
            v = fmaf(b_phi[k], wc, v);
        }
        su.p.ru[qd][d] = u;
        su.p.rv[qd][d] = v;
        __syncthreads();
        if (qd == 0) {
            g_u[d] = su.p.ru[0][d] + su.p.ru[1][d] + su.p.ru[2][d] + su.p.ru[3][d];
            g_v[d] = su.p.rv[0][d] + su.p.rv[1][d] + su.p.rv[2][d] + su.p.rv[3][d];
        }
        if (tid < BATCHES) {
            g_cnt[tid] = su.p.start[tid+1] - su.p.start[tid];
            float qq = q[tid];
            float c = cosf(6.283185307179586f*qq);
            float s = sinf(6.283185307179586f*qq);
            g_coef[tid] = (2.0f - c) / s;
        }
        #pragma unroll
        for (int l = 0; l < 4; l++) {
            int idx = tid + l*256;
            int bb = idx >> 7, pos = idx & 127;
            int cnt = su.p.start[bb+1] - su.p.start[bb];
            out_mask[idx] = (pos < cnt) ? 1.0f : 0.0f;
        }
        return;
    }
    // ---- main GEMM blocks: 64 rows x 64 cols, K=64, HMMA ----
    int row0 = blockIdx.y * 64;
    int col0 = blockIdx.x * 64;
    int bb = row0 >> 7;
    int sb_start = lbound(batch, TOTAL, bb);
    int sb_cnt   = lbound(batch, TOTAL, bb+1) - sb_start;

    // X fill: thread = (row r, k-quarter), 4 float4 -> 8 half2 STS
    {
        int r = tid >> 2, kq = (tid & 3) * 16;
        int pos = (row0 + r) & 127;
        #pragma unroll
        for (int i = 0; i < 4; i++) {
            float4 v = make_float4(0.f,0.f,0.f,0.f);
            if (pos < sb_cnt) v = *(const float4*)&x[(sb_start + pos)*PE + kq + i*4];
            __half2 h0 = __floats2half2_rn(v.x, v.y);
            __half2 h1 = __floats2half2_rn(v.z, v.w);
            *(__half2*)&su.g.Xs[r][kq + i*4]     = h0;
            *(__half2*)&su.g.Xs[r][kq + i*4 + 2] = h1;
        }
    }
    // W fill (transpose): thread = (k, n-quarter), reads coalesced, STS.16 scatter
    {
        int k = tid >> 2, nq = (tid & 3) * 16;
        #pragma unroll
        for (int i = 0; i < 4; i++) {
            float4 v = *(const float4*)&w[k*PROJC + col0 + nq + i*4];
            su.g.Ws[nq + i*4    ][k] = __float2half_rn(v.x);
            su.g.Ws[nq + i*4 + 1][k] = __float2half_rn(v.y);
            su.g.Ws[nq + i*4 + 2][k] = __float2half_rn(v.z);
            su.g.Ws[nq + i*4 + 3][k] = __float2half_rn(v.w);
        }
    }
    __syncthreads();

    int lane = tid & 31, wrp = tid >> 5;
    int gid = lane >> 2, tig = lane & 3;
    int mtile = wrp >> 1, nh = wrp & 1;         // warp: m16 x n32
    float acc[4][4];
    #pragma unroll
    for (int nt = 0; nt < 4; nt++)
        #pragma unroll
        for (int j = 0; j < 4; j++) acc[nt][j] = 0.f;
    #pragma unroll
    for (int kc = 0; kc < 4; kc++) {
        int k0 = kc*16 + 2*tig;
        int m0 = mtile*16;
        uint a0 = *(const uint*)&su.g.Xs[m0 + gid    ][k0];
        uint a1 = *(const uint*)&su.g.Xs[m0 + gid + 8][k0];
        uint a2 = *(const uint*)&su.g.Xs[m0 + gid    ][k0+8];
        uint a3 = *(const uint*)&su.g.Xs[m0 + gid + 8][k0+8];
        #pragma unroll
        for (int nt = 0; nt < 4; nt++) {
            int n = nh*32 + nt*8 + gid;
            uint b0 = *(const uint*)&su.g.Ws[n][k0];
            uint b1 = *(const uint*)&su.g.Ws[n][k0+8];
            HMMA16816(acc[nt][0], acc[nt][1], acc[nt][2], acc[nt][3],
                      a0, a1, a2, a3, b0, b1);
        }
    }
    // epilogue: add bias, zero invalid rows, store fp16
    #pragma unroll
    for (int rr = 0; rr < 2; rr++) {
        int r = row0 + mtile*16 + gid + 8*rr;
        int valid = ((r & 127) < sb_cnt);
        #pragma unroll
        for (int nt = 0; nt < 4; nt++) {
            int c = col0 + nh*32 + nt*8 + 2*tig;
            float v0 = 0.f, v1 = 0.f;
            if (valid) {
                v0 = acc[nt][2*rr]   + __ldg(&bias[c]);
                v1 = acc[nt][2*rr+1] + __ldg(&bias[c+1]);
            }
            *(__half2*)&g_projh[r*PROJC + c] = __floats2half2_rn(v0, v1);
        }
    }
}

// ---------------------------------------------------------------------------
// K2 (fused, HMMA, 256 threads): fp16 proj -> copy fills -> HMMA z ->
// row stats -> Chebyshev coeffs (C2 split over 224 threads) -> Clenshaw.
// ---------------------------------------------------------------------------
#define HPAD 136
struct SmemGemm { unsigned short Ks[16][HPAD]; unsigned short Qs[128][HPAD]; };
struct SmemEpi  {
    ull   a2[16][68];
    float nodp[2][16][16];
    ull   ck[16][14];
    ull   ws2[64];
    ull   w2d[64];
    float alpha[16], rho[16], zmax[16], rinv[16];
    float psum[16][8], pmax[16][8];
};

__global__ void __launch_bounds__(256) k_zmain(
        const float* __restrict__ w_self, const float* __restrict__ b_self,
        const float* __restrict__ w_out, const float* __restrict__ b_out,
        float* __restrict__ out_e, float* __restrict__ out_edge) {
    __shared__ union { SmemGemm g; SmemEpi e; } su;
    __shared__ float s_maskf[NMAX];
    const float scale = 0.05590169943749474f;   // 1/sqrt(320)
    int tid = threadIdx.x;
    int lane = tid & 31, w = tid >> 5;          // 8 warps
    int gid = lane >> 2, tig = lane & 3;
    int tile = blockIdx.x, e = blockIdx.y, b = blockIdx.z;
    int row0 = tile * 16;
    int base_row = b * NMAX;
    int cnt = g_cnt[b];
    float coef = g_coef[b];
    if (tid < NMAX) s_maskf[tid] = (tid < cnt) ? 1.0f : 0.0f;

    int koff1 = e*PE, koff2 = 2*NE*PE + e*PE;
    int qoff1 = NE*PE + e*PE, qoff2 = 3*NE*PE + e*PE;

    {   // K fill (coef folded into k2 half)
        int r = tid >> 4, c = tid & 15;
        const __half* src = (c < 8)
            ? &g_projh[(base_row + row0 + r)*PROJC + koff1 + c*8]
            : &g_projh[(base_row + row0 + r)*PROJC + koff2 + (c-8)*8];
        uint4 v = *(const uint4*)src;
        if (c >= 8) {
            __half2* hp = (__half2*)&v;
            #pragma unroll
            for (int t = 0; t < 4; t++) {
                float2 f = __half22float2(hp[t]);
                hp[t] = __floats2half2_rn(f.x*coef, f.y*coef);
            }
        }
        *(uint4*)&su.g.Ks[r][c*8] = v;
    }
    #pragma unroll
    for (int l = 0; l < 8; l++) {               // Q fill: pure 16B copy
        int e4 = tid + l*256;
        int m = e4 >> 4, c = e4 & 15;
        const __half* src = (c < 8)
            ? &g_projh[(base_row + m)*PROJC + qoff1 + c*8]
            : &g_projh[(base_row + m)*PROJC + qoff2 + (c-8)*8];
        *(uint4*)&su.g.Qs[m][c*8] = *(const uint4*)src;
    }
    __syncthreads();

    // ---- HMMA mainloop: M=16, N=16 (per warp), K=128 ----
    float acc[2][4];
    #pragma unroll
    for (int nt = 0; nt < 2; nt++)
        #pragma unroll
        for (int j = 0; j < 4; j++) acc[nt][j] = 0.f;
    #pragma unroll
    for (int kc = 0; kc < 8; kc++) {
        int k0 = kc*16 + 2*tig;
        uint a0 = *(const uint*)&su.g.Ks[gid  ][k0];
        uint a1 = *(const uint*)&su.g.Ks[gid+8][k0];
        uint a2 = *(const uint*)&su.g.Ks[gid  ][k0+8];
        uint a3 = *(const uint*)&su.g.Ks[gid+8][k0+8];
        #pragma unroll
        for (int nt = 0; nt < 2; nt++) {
            int n = 16*w + nt*8 + gid;
            uint b0 = *(const uint*)&su.g.Qs[n][k0];
            uint b1 = *(const uint*)&su.g.Qs[n][k0+8];
            HMMA16816(acc[nt][0], acc[nt][1], acc[nt][2], acc[nt][3],
                      a0, a1, a2, a3, b0, b1);
        }
    }
    #pragma unroll
    for (int nt = 0; nt < 2; nt++)
        #pragma unroll
        for (int j = 0; j < 4; j++) acc[nt][j] *= scale;

    __syncthreads();    // GEMM tiles dead; epilogue aliases su

    // ---- Phase B: row sums / zmax (fragment-aware) ----
    {
        int n0g = row0 + gid, n1g = row0 + gid + 8;
        float s0 = 0.f, s1 = 0.f, zm0 = 0.f, zm1 = 0.f;
        #pragma unroll
        for (int nt = 0; nt < 2; nt++) {
            int m = 16*w + nt*8 + 2*tig;
            float w0a = s_maskf[m]   * (float)(m   != n0g);
            float w0b = s_maskf[m+1] * (float)(m+1 != n0g);
            float w1a = s_maskf[m]   * (float)(m   != n1g);
            float w1b = s_maskf[m+1] * (float)(m+1 != n1g);
            s0 = fmaf(acc[nt][0], w0a, fmaf(acc[nt][1], w0b, s0));
            s1 = fmaf(acc[nt][2], w1a, fmaf(acc[nt][3], w1b, s1));
            zm0 = fmaxf(zm0, fmaxf(fabsf(acc[nt][0]), fabsf(acc[nt][1])));
            zm1 = fmaxf(zm1, fmaxf(fabsf(acc[nt][2]), fabsf(acc[nt][3])));
        }
        #pragma unroll
        for (int off = 1; off <= 2; off <<= 1) {
            s0 += __shfl_xor_sync(0xffffffffu, s0, off);
            s1 += __shfl_xor_sync(0xffffffffu, s1, off);
            zm0 = fmaxf(zm0, __shfl_xor_sync(0xffffffffu, zm0, off));
            zm1 = fmaxf(zm1, __shfl_xor_sync(0xffffffffu, zm1, off));
        }
        if (tig == 0) {
            su.e.psum[gid  ][w] = s0;
            su.e.psum[gid+8][w] = s1;
            su.e.pmax[gid  ][w] = zm0;
            su.e.pmax[gid+8][w] = zm1;
        }
        if (tid >= 128 && tid < 192) {
            int d = tid - 128;
            su.e.ws2[d] = dup2(w_self[d]);
            su.e.w2d[d] = dup2(0.5f * w_out[d]);
        }
    }
    __syncthreads();
    if (tid < 16) {
        int r = tid;
        float s = 0.f, zm = 0.f;
        #pragma unroll
        for (int j = 0; j < 8; j++) {
            s += su.e.psum[r][j];
            zm = fmaxf(zm, su.e.pmax[r][j]);
        }
        int mn = ((row0 + r) < cnt);
        float cm1 = (float)(cnt - 1);
        float denom = fmaxf(cm1, 1.0f);
        su.e.alpha[r] = mn ? (s / denom) : 0.0f;
        su.e.rho[r]   = mn ? (cm1 / denom) : 0.0f;
        float zmx = fmaxf(zm, 1e-20f);
        su.e.zmax[r]  = zmx;
        su.e.rinv[r]  = 1.0f / zmx;
    }
    __syncthreads();

    // ---- Phase C1: per-row gelu offsets (pre-dup2'd, padded) ----
    #pragma unroll
    for (int l = 0; l < 4; l++) {
        int idx = tid + l*256;
        int row = idx >> 6, d = idx & 63;
        float av = fmaf(su.e.alpha[row], g_u[d],
                        fmaf(su.e.rho[row], g_v[d], b_self[d]));
        su.e.a2[row][d] = dup2(av);
    }
    __syncthreads();

    // ---- Phase C2: nodal partial sums, 224 threads (row x np x d-half) ----
    if (tid < 224) {
        int row = tid / 14;
        int rem = tid - row*14;
        int np = rem % 7, half = rem / 7;
        int d0 = half * 32;
        float zmaxr = su.e.zmax[row];
        float znl = zmaxr * g_cheb[2*np];
        float znh = zmaxr * g_cheb[2*np+1];
        ull zn; PACK2(zn, znl, znh);
        const ull k0 = dup2(C0), k1 = dup2(C1), k2 = dup2(C2);
        const ull k3 = dup2(C3), k4 = dup2(C4), k5 = dup2(C5);
        ull acc2 = 0ull;
        float tmax = 0.f;
        #pragma unroll 8
        for (int d = d0; d < d0 + 32; d++) {
            ull ad = su.e.a2[row][d];
            ull xx, tt, p;
            FMA2(xx, su.e.ws2[d], zn, ad);
            MUL2(tt, xx, xx);
            p = k5;
            FMA2(p, p, tt, k4);
            FMA2(p, p, tt, k3);
            FMA2(p, p, tt, k2);
            FMA2(p, p, tt, k1);
            FMA2(p, p, tt, k0);
            ull h;
            FMA2(h, tt, p, xx);
            FMA2(acc2, su.e.w2d[d], h, acc2);
            tmax = fmaxf(tmax, fmaxf(lo2(tt), hi2(tt)));
        }
        if (tmax > 2.25f) {
            float al = 0.f, ah = 0.f;
            for (int d = d0; d < d0 + 32; d++) {
                float a = lo2(su.e.a2[row][d]);
                float ws = lo2(su.e.ws2[d]);
                float w2 = lo2(su.e.w2d[d]);
                float x0 = fmaf(ws, znl, a), x1 = fmaf(ws, znh, a);
                al = fmaf(w2, x0*(1.f + erff(x0*0.7071067811865476f)), al);
                ah = fmaf(w2, x1*(1.f + erff(x1*0.7071067811865476f)), ah);
            }
            PACK2(acc2, al, ah);
        }
        su.e.nodp[half][row][2*np]   = lo2(acc2);
        su.e.nodp[half][row][2*np+1] = hi2(acc2);
    }
    __syncthreads();

    // ---- Phase C3: DCT over combined halves (b_out folded into c0) ----
    float bo = b_out[0];
    if (tid < 224) {
        int row = tid / 14, k = tid - row*14;
        float c = 0.f;
        #pragma unroll
        for (int j = 0; j < 14; j++)
            c = fmaf(__ldg(&g_dct[k*14 + j]),
                     su.e.nodp[0][row][j] + su.e.nodp[1][row][j], c);
        if (k == 0) c += bo;
        su.e.ck[row][k] = dup2(c);
    }
    __syncthreads();

    // ---- Phase D: packed Clenshaw on register fragments + stores ----
    ull negone = dup2(-1.0f);
    #pragma unroll
    for (int rr = 0; rr < 2; rr++) {
        int rloc = gid + 8*rr;
        int n = row0 + rloc;
        ull rinv2 = dup2(su.e.rinv[rloc]);
        ull sv[2], svx[2], b1[2], b2[2];
        #pragma unroll
        for (int nt = 0; nt < 2; nt++) {
            ull z2; PACK2(z2, acc[nt][2*rr], acc[nt][2*rr+1]);
            MUL2(sv[nt], z2, rinv2);
            ADD2(svx[nt], sv[nt], sv[nt]);
            b1[nt] = 0ull; b2[nt] = 0ull;
        }
        #pragma unroll
        for (int k = 13; k >= 1; k--) {
            ull ckk = su.e.ck[rloc][k];
            #pragma unroll
            for (int nt = 0; nt < 2; nt++) {
                ull nb;
                FMA2(nb, svx[nt], b1[nt], ckk);
                FMA2(nb, b2[nt], negone, nb);
                b2[nt] = b1[nt]; b1[nt] = nb;
            }
        }
        ull ck0 = su.e.ck[rloc][0];
        #pragma unroll
        for (int nt = 0; nt < 2; nt++) {
            ull f;
            FMA2(f, sv[nt], b1[nt], ck0);
            FMA2(f, b2[nt], negone, f);
            int m = 16*w + nt*8 + 2*tig;
            out_e[((long)(b*NMAX + m  )*NMAX + n)*NE + e] = lo2(f);
            out_e[((long)(b*NMAX + m+1)*NMAX + n)*NE + e] = hi2(f);
        }
        if (e == 0) {
            float mkn = s_maskf[n];
            #pragma unroll
            for (int nt = 0; nt < 2; nt++) {
                int m = 16*w + nt*8 + 2*tig;
                float2 v = make_float2(mkn*s_maskf[m]  *(float)(n != m),
                                       mkn*s_maskf[m+1]*(float)(n != m+1));
                *(float2*)&out_edge[(b*NMAX + n)*NMAX + m] = v;
            }
        }
    }
}

extern "C" void kernel_launch(void* const* d_in, const int* in_sizes, int n_in,
                              void* d_out, int out_size) {
    const float* x      = (const float*)d_in[0];
    const int*   batch  = (const int*)  d_in[1];
    const float* q      = (const float*)d_in[2];
    const float* w_attn = (const float*)d_in[3];
    const float* b_attn = (const float*)d_in[4];
    const float* w_node = (const float*)d_in[5];
    const float* b_node = (const float*)d_in[6];
    const float* w_phi  = (const float*)d_in[7];
    const float* b_phi  = (const float*)d_in[8];
    const float* w_ctx  = (const float*)d_in[9];
    const float* w_self = (const float*)d_in[10];
    const float* b_self = (const float*)d_in[11];
    const float* w_out  = (const float*)d_in[12];
    const float* b_out  = (const float*)d_in[13];
    float* out = (float*)d_out;

    k_projx<<<dim3(22, 16), 256>>>(x, w_attn, b_attn, w_node, b_node,
                                   batch, q, w_phi, b_phi, w_ctx,
                                   out + OFF_XHAT, out + OFF_MASK);
    k_zmain<<<dim3(8, NE, BATCHES), 256>>>(w_self, b_self, w_out, b_out,
                                           out + OFF_EHAT, out + OFF_EDGE);
}